// round 15
// baseline (speedup 1.0000x reference)
#include <cuda_runtime.h>
#include <cuda_bf16.h>
#include <stdint.h>
#include <math.h>

typedef unsigned int u32;

// ---------------- problem constants (match setup_inputs) ----------------
#define BATCH  2
#define TSEQ   2048
#define CDIM   1024
#define VDIM   8192
#define LAYERS 2
#define NHEAD  16
#define HD     64
#define BT     (BATCH * TSEQ)   // 4096 rows

// ---------------- scratch (device globals: allocation-free) -------------
__device__ float g_h[BT * CDIM];
__device__ float g_logits[(size_t)BT * VDIM];
__device__ float g_nll[BT];

__device__ __nv_bfloat16 g_ahi[BT * CDIM];
__device__ __nv_bfloat16 g_alo[BT * CDIM];
__device__ __nv_bfloat16 g_qhi[BT * CDIM];
__device__ __nv_bfloat16 g_qlo[BT * CDIM];
__device__ __nv_bfloat16 g_khi[BT * CDIM];
__device__ __nv_bfloat16 g_klo[BT * CDIM];
__device__ __nv_bfloat16 g_vthi[BT * CDIM];  // transposed: [(b,c)][token]
__device__ __nv_bfloat16 g_vtlo[BT * CDIM];
__device__ __nv_bfloat16 g_chi[BT * CDIM];
__device__ __nv_bfloat16 g_clo[BT * CDIM];

__device__ __nv_bfloat16 g_wqhi[LAYERS * CDIM * CDIM];
__device__ __nv_bfloat16 g_wqlo[LAYERS * CDIM * CDIM];
__device__ __nv_bfloat16 g_wkhi[LAYERS * CDIM * CDIM];
__device__ __nv_bfloat16 g_wklo[LAYERS * CDIM * CDIM];
__device__ __nv_bfloat16 g_wvhi[LAYERS * CDIM * CDIM];
__device__ __nv_bfloat16 g_wvlo[LAYERS * CDIM * CDIM];
__device__ __nv_bfloat16 g_wohi[LAYERS * CDIM * CDIM];
__device__ __nv_bfloat16 g_wolo[LAYERS * CDIM * CDIM];
__device__ __nv_bfloat16 g_wuhi[(size_t)VDIM * CDIM];
__device__ __nv_bfloat16 g_wulo[(size_t)VDIM * CDIM];

// ---------------- fused fp32 -> bf16 hi/lo split of ALL weights -----------
#define WCC  (LAYERS * CDIM * CDIM)         // 2097152 = 2^21
#define WTOT (4 * WCC + VDIM * CDIM)        // 16777216

struct SplitArgs {
    const float* src[5];
    __nv_bfloat16* hi[5];
    __nv_bfloat16* lo[5];
};

__global__ void split_all_kernel(SplitArgs a) {
    size_t i = (size_t)blockIdx.x * blockDim.x + threadIdx.x;
    if (i >= WTOT) return;
    int w; size_t off;
    if (i < (size_t)4 * WCC) { w = (int)(i >> 21); off = i & (WCC - 1); }
    else                     { w = 4; off = i - (size_t)4 * WCC; }
    float x = a.src[w][off];
    __nv_bfloat16 h = __float2bfloat16(x);
    a.hi[w][off] = h;
    a.lo[w][off] = __float2bfloat16(x - __bfloat162float(h));
}

// ---------------- embedding + positional (+ hi/lo) ------------------------
__global__ void embed_kernel(const int* __restrict__ x,
                             const float* __restrict__ embed_w,
                             const float* __restrict__ pos) {
    size_t i = (size_t)blockIdx.x * blockDim.x + threadIdx.x;
    size_t total = (size_t)BT * CDIM;
    if (i >= total) return;
    int c  = (int)(i % CDIM);
    size_t bt = i / CDIM;
    int t  = (int)(bt % TSEQ);
    int tok = x[bt];
    float val = embed_w[(size_t)tok * CDIM + c] + pos[(size_t)t * CDIM + c];
    g_h[i] = val;
    __nv_bfloat16 hb = __float2bfloat16(val);
    g_ahi[i] = hb;
    g_alo[i] = __float2bfloat16(val - __bfloat162float(hb));
}

// ---------------- shared helpers ------------------------------------------
__device__ __forceinline__ void cp16(u32 s, const void* g) {
    asm volatile("cp.async.cg.shared.global [%0], [%1], 16;\n" :: "r"(s), "l"(g));
}
__device__ __forceinline__ void mma_bf16(float* d, const u32* a, const u32* b) {
    asm volatile(
        "mma.sync.aligned.m16n8k16.row.col.f32.bf16.bf16.f32 "
        "{%0,%1,%2,%3}, {%4,%5,%6,%7}, {%8,%9}, {%0,%1,%2,%3};\n"
        : "+f"(d[0]), "+f"(d[1]), "+f"(d[2]), "+f"(d[3])
        : "r"(a[0]), "r"(a[1]), "r"(a[2]), "r"(a[3]), "r"(b[0]), "r"(b[1]));
}
__device__ __forceinline__ void ldm4(u32* r, u32 a) {
    asm volatile("ldmatrix.sync.aligned.m8n8.x4.shared.b16 {%0,%1,%2,%3}, [%4];"
                 : "=r"(r[0]), "=r"(r[1]), "=r"(r[2]), "=r"(r[3]) : "r"(a));
}
__device__ __forceinline__ u32 pk2(float x, float y) {
    __nv_bfloat162 p = __floats2bfloat162_rn(x, y);
    return *(u32*)&p;
}

// ---------------- GEMM tile config ----------------------------------------
#define GT 256
#define RS      80
#define ARRB    (128 * RS)
#define STAGE   (4 * ARRB)
#define GSMEM   (2 * STAGE)              // 81920

// ---------------- fused QKV GEMM ------------------------------------------
struct QKVArgs {
    const __nv_bfloat16 *Ahi, *Alo;
    const __nv_bfloat16 *Wh[3], *Wl[3];
    const float *bias[3];
    __nv_bfloat16 *ohi[3], *olo[3];
};

__global__ __launch_bounds__(GT)
void gemm_qkv(QKVArgs args) {
    extern __shared__ char smraw[];
    u32 sbase = (u32)__cvta_generic_to_shared(smraw);

    int tid = threadIdx.x;
    int lane = tid & 31, wid = tid >> 5;
    int warp_m = wid & 1, warp_n = wid >> 1;
    int wsel = (int)(blockIdx.x >> 3);          // 0:Q 1:K 2:V
    int m0 = blockIdx.y * 128, n0 = (int)(blockIdx.x & 7) * 128;
    int g = lane >> 2, t2 = (lane & 3) * 2;
    const int N = CDIM, K = CDIM;

    const __nv_bfloat16* Ahi = args.Ahi;
    const __nv_bfloat16* Alo = args.Alo;
    const __nv_bfloat16* Whi = args.Wh[wsel];
    const __nv_bfloat16* Wlo = args.Wl[wsel];

    float acc[4][4][4];
#pragma unroll
    for (int i = 0; i < 4; i++)
#pragma unroll
        for (int j = 0; j < 4; j++)
#pragma unroll
            for (int r = 0; r < 4; r++) acc[i][j][r] = 0.f;

    int NKB = K >> 5;
    auto issue_loads = [&](int kb, int s) {
        int kk = kb << 5;
        u32 st = sbase + s * STAGE;
#pragma unroll
        for (int ii = 0; ii < 8; ii++) {
            int i = tid + ii * GT;
            int arr = i >> 9, rem = i & 511;
            int r = rem >> 2, gg = rem & 3;
            const __nv_bfloat16* src = (arr == 0) ? Ahi : (arr == 1) ? Alo
                                      : (arr == 2) ? Whi : Wlo;
            int row = ((arr < 2) ? m0 : n0) + r;
            u32 dst = st + (u32)arr * ARRB + (u32)(r * RS + gg * 16);
            cp16(dst, src + (size_t)row * K + kk + gg * 8);
        }
    };

    issue_loads(0, 0);
    asm volatile("cp.async.commit_group;\n");
    issue_loads(1, 1);
    asm volatile("cp.async.commit_group;\n");

    for (int kb = 0; kb < NKB; kb++) {
        if (kb + 1 < NKB) asm volatile("cp.async.wait_group 1;\n" ::: "memory");
        else              asm volatile("cp.async.wait_group 0;\n" ::: "memory");
        __syncthreads();
        u32 st = sbase + (kb & 1) * STAGE;

#pragma unroll
        for (int ks = 0; ks < 2; ks++) {
            int kby = ks * 32;
            u32 ah[4][4], al[4][4];
#pragma unroll
            for (int mi = 0; mi < 4; mi++) {
                u32 arow = st + (u32)((warp_m * 64 + mi * 16 + (lane & 15)) * RS
                                      + kby + (lane >> 4) * 16);
                ldm4(ah[mi], arow);
                ldm4(al[mi], arow + ARRB);
            }
            u32 bh[2][4], bl[2][4];
#pragma unroll
            for (int kh = 0; kh < 2; kh++) {
                u32 brow = st + 2 * ARRB + (u32)((warp_n * 32 + lane) * RS
                                                 + kby + kh * 16);
                ldm4(bh[kh], brow);
                ldm4(bl[kh], brow + ARRB);
            }
            u32 bfh[4][2], bfl[4][2];
#pragma unroll
            for (int ni = 0; ni < 4; ni++) {
                bfh[ni][0] = bh[0][ni]; bfh[ni][1] = bh[1][ni];
                bfl[ni][0] = bl[0][ni]; bfl[ni][1] = bl[1][ni];
            }
#pragma unroll
            for (int mi = 0; mi < 4; mi++)
#pragma unroll
                for (int ni = 0; ni < 4; ni++)
                    mma_bf16(acc[mi][ni], ah[mi], bfh[ni]);
#pragma unroll
            for (int mi = 0; mi < 4; mi++)
#pragma unroll
                for (int ni = 0; ni < 4; ni++)
                    mma_bf16(acc[mi][ni], ah[mi], bfl[ni]);
#pragma unroll
            for (int mi = 0; mi < 4; mi++)
#pragma unroll
                for (int ni = 0; ni < 4; ni++)
                    mma_bf16(acc[mi][ni], al[mi], bfh[ni]);
        }
        __syncthreads();
        if (kb + 2 < NKB) {
            issue_loads(kb + 2, kb & 1);
            asm volatile("cp.async.commit_group;\n");
        }
    }

    const float* bias = args.bias[wsel];
    __nv_bfloat16* ohi = args.ohi[wsel];
    __nv_bfloat16* olo = args.olo[wsel];
    int vtrans = (wsel == 2);

    auto emit = [&](int m, int cc, float val) {
        __nv_bfloat16 hb = __float2bfloat16(val);
        __nv_bfloat16 lb = __float2bfloat16(val - __bfloat162float(hb));
        size_t idx = vtrans
            ? ((size_t)((m >> 11) * N + cc)) * TSEQ + (m & 2047)
            : (size_t)m * N + cc;
        ohi[idx] = hb;
        olo[idx] = lb;
    };
#pragma unroll
    for (int mi = 0; mi < 4; mi++) {
        int r0 = m0 + warp_m * 64 + mi * 16 + g;
#pragma unroll
        for (int ni = 0; ni < 4; ni++) {
            int c = n0 + warp_n * 32 + ni * 8 + t2;
            float b0 = bias[c], b1 = bias[c + 1];
            emit(r0, c, acc[mi][ni][0] + b0);
            emit(r0, c + 1, acc[mi][ni][1] + b1);
            emit(r0 + 8, c, acc[mi][ni][2] + b0);
            emit(r0 + 8, c + 1, acc[mi][ni][3] + b1);
        }
    }
}

// ---------------- generic bf16x3 GEMM (Wo, logits) -------------------------
__global__ __launch_bounds__(GT)
void gemm_bf16x3(const __nv_bfloat16* __restrict__ Ahi, const __nv_bfloat16* __restrict__ Alo,
                 const __nv_bfloat16* __restrict__ Whi, const __nv_bfloat16* __restrict__ Wlo,
                 const float* __restrict__ bias, const float* __restrict__ res,
                 float* __restrict__ outf,
                 __nv_bfloat16* __restrict__ ohi, __nv_bfloat16* __restrict__ olo,
                 int M, int N, int K) {
    extern __shared__ char smraw[];
    u32 sbase = (u32)__cvta_generic_to_shared(smraw);

    int tid = threadIdx.x;
    int lane = tid & 31, wid = tid >> 5;
    int warp_m = wid & 1, warp_n = wid >> 1;
    int m0 = blockIdx.y * 128, n0 = blockIdx.x * 128;
    int g = lane >> 2, t2 = (lane & 3) * 2;

    float acc[4][4][4];
#pragma unroll
    for (int i = 0; i < 4; i++)
#pragma unroll
        for (int j = 0; j < 4; j++)
#pragma unroll
            for (int r = 0; r < 4; r++) acc[i][j][r] = 0.f;

    int NKB = K >> 5;
    auto issue_loads = [&](int kb, int s) {
        int kk = kb << 5;
        u32 st = sbase + s * STAGE;
#pragma unroll
        for (int ii = 0; ii < 8; ii++) {
            int i = tid + ii * GT;
            int arr = i >> 9, rem = i & 511;
            int r = rem >> 2, gg = rem & 3;
            const __nv_bfloat16* src = (arr == 0) ? Ahi : (arr == 1) ? Alo
                                      : (arr == 2) ? Whi : Wlo;
            int row = ((arr < 2) ? m0 : n0) + r;
            u32 dst = st + (u32)arr * ARRB + (u32)(r * RS + gg * 16);
            cp16(dst, src + (size_t)row * K + kk + gg * 8);
        }
    };

    issue_loads(0, 0);
    asm volatile("cp.async.commit_group;\n");
    issue_loads(1, 1);
    asm volatile("cp.async.commit_group;\n");

    for (int kb = 0; kb < NKB; kb++) {
        if (kb + 1 < NKB) asm volatile("cp.async.wait_group 1;\n" ::: "memory");
        else              asm volatile("cp.async.wait_group 0;\n" ::: "memory");
        __syncthreads();
        u32 st = sbase + (kb & 1) * STAGE;

#pragma unroll
        for (int ks = 0; ks < 2; ks++) {
            int kby = ks * 32;
            u32 ah[4][4], al[4][4];
#pragma unroll
            for (int mi = 0; mi < 4; mi++) {
                u32 arow = st + (u32)((warp_m * 64 + mi * 16 + (lane & 15)) * RS
                                      + kby + (lane >> 4) * 16);
                ldm4(ah[mi], arow);
                ldm4(al[mi], arow + ARRB);
            }
            u32 bh[2][4], bl[2][4];
#pragma unroll
            for (int kh = 0; kh < 2; kh++) {
                u32 brow = st + 2 * ARRB + (u32)((warp_n * 32 + lane) * RS
                                                 + kby + kh * 16);
                ldm4(bh[kh], brow);
                ldm4(bl[kh], brow + ARRB);
            }
            u32 bfh[4][2], bfl[4][2];
#pragma unroll
            for (int ni = 0; ni < 4; ni++) {
                bfh[ni][0] = bh[0][ni]; bfh[ni][1] = bh[1][ni];
                bfl[ni][0] = bl[0][ni]; bfl[ni][1] = bl[1][ni];
            }
#pragma unroll
            for (int mi = 0; mi < 4; mi++)
#pragma unroll
                for (int ni = 0; ni < 4; ni++)
                    mma_bf16(acc[mi][ni], ah[mi], bfh[ni]);
#pragma unroll
            for (int mi = 0; mi < 4; mi++)
#pragma unroll
                for (int ni = 0; ni < 4; ni++)
                    mma_bf16(acc[mi][ni], ah[mi], bfl[ni]);
#pragma unroll
            for (int mi = 0; mi < 4; mi++)
#pragma unroll
                for (int ni = 0; ni < 4; ni++)
                    mma_bf16(acc[mi][ni], al[mi], bfh[ni]);
        }
        __syncthreads();
        if (kb + 2 < NKB) {
            issue_loads(kb + 2, kb & 1);
            asm volatile("cp.async.commit_group;\n");
        }
    }

    auto emit = [&](int m, int cc, float val) {
        if (outf) outf[(size_t)m * N + cc] = val;
        if (ohi) {
            __nv_bfloat16 hb = __float2bfloat16(val);
            __nv_bfloat16 lb = __float2bfloat16(val - __bfloat162float(hb));
            size_t idx = (size_t)m * N + cc;
            ohi[idx] = hb;
            olo[idx] = lb;
        }
    };
#pragma unroll
    for (int mi = 0; mi < 4; mi++) {
        int r0 = m0 + warp_m * 64 + mi * 16 + g;
#pragma unroll
        for (int ni = 0; ni < 4; ni++) {
            int c = n0 + warp_n * 32 + ni * 8 + t2;
            float v0 = acc[mi][ni][0], v1 = acc[mi][ni][1];
            float v2 = acc[mi][ni][2], v3 = acc[mi][ni][3];
            if (bias) { float b0 = bias[c], b1 = bias[c + 1]; v0 += b0; v1 += b1; v2 += b0; v3 += b1; }
            if (res) {
                v0 += res[(size_t)r0 * N + c];       v1 += res[(size_t)r0 * N + c + 1];
                v2 += res[(size_t)(r0 + 8) * N + c]; v3 += res[(size_t)(r0 + 8) * N + c + 1];
            }
            emit(r0, c, v0);     emit(r0, c + 1, v1);
            emit(r0 + 8, c, v2); emit(r0 + 8, c + 1, v3);
        }
    }
}

// ---------------- MMA flash attention (R13 scheduling, 2 CTAs/SM) ----------
// CTA: 128 queries (8 warps x 16); KV tiles of 64 keys, double-buffered.
// Grid 16x32 = 512 CTAs, longest-first; launch_bounds caps regs for 2 CTAs/SM.
#define APAD 72
#define QSZB (128 * APAD * 2)
#define KSZB (64 * APAD * 2)
#define STGB (4 * KSZB)
#define ASMEM (2 * QSZB + 2 * STGB)  // 110592
#define NQT  (TSEQ / 128)            // 16

__global__ __launch_bounds__(256, 2)
void attn_mma_kernel() {
    extern __shared__ char araw[];
    u32 sb = (u32)__cvta_generic_to_shared(araw);
    __nv_bfloat16* Qh = (__nv_bfloat16*)araw;
    __nv_bfloat16* Ql = Qh + 128 * APAD;

    int tid = threadIdx.x, lane = tid & 31, wq = tid >> 5;
    int g = lane >> 2, t = lane & 3;
    int b = blockIdx.y >> 4, hh = blockIdx.y & 15;
    int qt = (int)(gridDim.x - 1 - blockIdx.x);   // longest CTAs first
    int nkv = 2 * qt + 2;

    {
        size_t qb = ((size_t)(b * TSEQ + qt * 128)) * CDIM + hh * HD;
#pragma unroll
        for (int ii = 0; ii < 8; ii++) {
            int i = tid + ii * 256;
            int arr = i >> 10, rem = i & 1023;
            int r = rem >> 3, gg = rem & 7;
            const __nv_bfloat16* src = (arr ? g_qlo : g_qhi) + qb + (size_t)r * CDIM + gg * 8;
            cp16(sb + (u32)arr * QSZB + (u32)(r * (APAD * 2) + gg * 16), src);
        }
    }
    auto load_kv = [&](int kt, int st) {
        u32 base = sb + 2 * QSZB + (u32)st * STGB;
        size_t kb = ((size_t)(b * TSEQ + kt * 64)) * CDIM + hh * HD;
        size_t vb = ((size_t)(b * CDIM + hh * HD)) * TSEQ + kt * 64;
#pragma unroll
        for (int ii = 0; ii < 8; ii++) {
            int i = tid + ii * 256;
            int arr = i >> 9, rem = i & 511;
            int r = rem >> 3, gg = rem & 7;
            const __nv_bfloat16* src;
            if (arr == 0)      src = g_khi  + kb + (size_t)r * CDIM + gg * 8;
            else if (arr == 1) src = g_klo  + kb + (size_t)r * CDIM + gg * 8;
            else if (arr == 2) src = g_vthi + vb + (size_t)r * TSEQ + gg * 8;
            else               src = g_vtlo + vb + (size_t)r * TSEQ + gg * 8;
            cp16(base + (u32)arr * KSZB + (u32)(r * (APAD * 2) + gg * 16), src);
        }
    };
    load_kv(0, 0);
    asm volatile("cp.async.commit_group;\n");   // group: Q + KV0
    load_kv(1, 1);
    asm volatile("cp.async.commit_group;\n");   // group: KV1

    u32 qah[4][4], qal[4][4];
    float m0r = -1e30f, m1r = -1e30f, l0 = 0.f, l1 = 0.f;
    float o[8][4];
#pragma unroll
    for (int nt = 0; nt < 8; nt++)
#pragma unroll
        for (int i = 0; i < 4; i++) o[nt][i] = 0.f;

    for (int kt = 0; kt < nkv; kt++) {
        if (kt + 1 < nkv) asm volatile("cp.async.wait_group 1;\n" ::: "memory");
        else              asm volatile("cp.async.wait_group 0;\n" ::: "memory");
        __syncthreads();

        if (kt == 0) {
#pragma unroll
            for (int kb2 = 0; kb2 < 4; kb2++) {
                int r = wq * 16 + g, kk = kb2 * 16 + t * 2;
                qah[kb2][0] = *(const u32*)&Qh[r * APAD + kk];
                qah[kb2][1] = *(const u32*)&Qh[(r + 8) * APAD + kk];
                qah[kb2][2] = *(const u32*)&Qh[r * APAD + kk + 8];
                qah[kb2][3] = *(const u32*)&Qh[(r + 8) * APAD + kk + 8];
                qal[kb2][0] = *(const u32*)&Ql[r * APAD + kk];
                qal[kb2][1] = *(const u32*)&Ql[(r + 8) * APAD + kk];
                qal[kb2][2] = *(const u32*)&Ql[r * APAD + kk + 8];
                qal[kb2][3] = *(const u32*)&Ql[(r + 8) * APAD + kk + 8];
            }
        }

        __nv_bfloat16* Kh = (__nv_bfloat16*)(araw + 2 * QSZB + (kt & 1) * STGB);
        __nv_bfloat16* Kl = Kh + 64 * APAD;
        __nv_bfloat16* Vh = Kl + 64 * APAD;
        __nv_bfloat16* Vl = Vh + 64 * APAD;

        float s[8][4];
#pragma unroll
        for (int nt = 0; nt < 8; nt++)
#pragma unroll
            for (int i = 0; i < 4; i++) s[nt][i] = 0.f;

#pragma unroll
        for (int kb2 = 0; kb2 < 4; kb2++) {
            u32 kh2[8][2], kl2[8][2];
#pragma unroll
            for (int nt = 0; nt < 8; nt++) {
                int off = (nt * 8 + g) * APAD + kb2 * 16 + t * 2;
                kh2[nt][0] = *(const u32*)&Kh[off];
                kh2[nt][1] = *(const u32*)&Kh[off + 8];
                kl2[nt][0] = *(const u32*)&Kl[off];
                kl2[nt][1] = *(const u32*)&Kl[off + 8];
            }
#pragma unroll
            for (int nt = 0; nt < 8; nt++) mma_bf16(s[nt], qah[kb2], kh2[nt]);
#pragma unroll
            for (int nt = 0; nt < 8; nt++) mma_bf16(s[nt], qah[kb2], kl2[nt]);
#pragma unroll
            for (int nt = 0; nt < 8; nt++) mma_bf16(s[nt], qal[kb2], kh2[nt]);
        }

#pragma unroll
        for (int nt = 0; nt < 8; nt++) {
            s[nt][0] *= 0.125f; s[nt][1] *= 0.125f;
            s[nt][2] *= 0.125f; s[nt][3] *= 0.125f;
        }
        if (kt >= 2 * qt) {
            int rg0 = qt * 128 + wq * 16 + g, rg1 = rg0 + 8;
#pragma unroll
            for (int nt = 0; nt < 8; nt++) {
                int cg = kt * 64 + nt * 8 + t * 2;
                if (cg > rg0)     s[nt][0] = -1e30f;
                if (cg + 1 > rg0) s[nt][1] = -1e30f;
                if (cg > rg1)     s[nt][2] = -1e30f;
                if (cg + 1 > rg1) s[nt][3] = -1e30f;
            }
        }

        float tm0 = -1e30f, tm1 = -1e30f;
#pragma unroll
        for (int nt = 0; nt < 8; nt++) {
            tm0 = fmaxf(tm0, fmaxf(s[nt][0], s[nt][1]));
            tm1 = fmaxf(tm1, fmaxf(s[nt][2], s[nt][3]));
        }
        tm0 = fmaxf(tm0, __shfl_xor_sync(0xffffffffu, tm0, 1));
        tm0 = fmaxf(tm0, __shfl_xor_sync(0xffffffffu, tm0, 2));
        tm1 = fmaxf(tm1, __shfl_xor_sync(0xffffffffu, tm1, 1));
        tm1 = fmaxf(tm1, __shfl_xor_sync(0xffffffffu, tm1, 2));

        float mn0 = fmaxf(m0r, tm0), mn1 = fmaxf(m1r, tm1);
        float cf0 = __expf(m0r - mn0), cf1 = __expf(m1r - mn1);
        l0 *= cf0; l1 *= cf1;
#pragma unroll
        for (int nt = 0; nt < 8; nt++) {
            o[nt][0] *= cf0; o[nt][1] *= cf0;
            o[nt][2] *= cf1; o[nt][3] *= cf1;
        }
        m0r = mn0; m1r = mn1;

        float rs0 = 0.f, rs1 = 0.f;
#pragma unroll
        for (int nt = 0; nt < 8; nt++) {
            s[nt][0] = __expf(s[nt][0] - mn0);
            s[nt][1] = __expf(s[nt][1] - mn0);
            s[nt][2] = __expf(s[nt][2] - mn1);
            s[nt][3] = __expf(s[nt][3] - mn1);
            rs0 += s[nt][0] + s[nt][1];
            rs1 += s[nt][2] + s[nt][3];
        }
        rs0 += __shfl_xor_sync(0xffffffffu, rs0, 1);
        rs0 += __shfl_xor_sync(0xffffffffu, rs0, 2);
        rs1 += __shfl_xor_sync(0xffffffffu, rs1, 1);
        rs1 += __shfl_xor_sync(0xffffffffu, rs1, 2);
        l0 += rs0; l1 += rs1;

        u32 pah[4][4];
#pragma unroll
        for (int kb2 = 0; kb2 < 4; kb2++) {
            float* sa = s[2 * kb2];
            float* sb2 = s[2 * kb2 + 1];
            pah[kb2][0] = pk2(sa[0], sa[1]);
            pah[kb2][1] = pk2(sa[2], sa[3]);
            pah[kb2][2] = pk2(sb2[0], sb2[1]);
            pah[kb2][3] = pk2(sb2[2], sb2[3]);
        }

#pragma unroll
        for (int kb2 = 0; kb2 < 4; kb2++) {
            u32 vh2[8][2], vl2[8][2];
#pragma unroll
            for (int nt = 0; nt < 8; nt++) {
                int off = (nt * 8 + g) * APAD + kb2 * 16 + t * 2;
                vh2[nt][0] = *(const u32*)&Vh[off];
                vh2[nt][1] = *(const u32*)&Vh[off + 8];
                vl2[nt][0] = *(const u32*)&Vl[off];
                vl2[nt][1] = *(const u32*)&Vl[off + 8];
            }
#pragma unroll
            for (int nt = 0; nt < 8; nt++) mma_bf16(o[nt], pah[kb2], vh2[nt]);
#pragma unroll
            for (int nt = 0; nt < 8; nt++) mma_bf16(o[nt], pah[kb2], vl2[nt]);
        }

        __syncthreads();
        if (kt + 2 < nkv) {
            load_kv(kt + 2, kt & 1);
            asm volatile("cp.async.commit_group;\n");
        }
    }

    float inv0 = 1.0f / l0, inv1 = 1.0f / l1;
    int r0 = qt * 128 + wq * 16 + g;
    size_t ob0 = ((size_t)(b * TSEQ + r0)) * CDIM + hh * HD;
    size_t ob1 = ((size_t)(b * TSEQ + r0 + 8)) * CDIM + hh * HD;
#pragma unroll
    for (int nt = 0; nt < 8; nt++) {
        int c = nt * 8 + t * 2;
        float v0 = o[nt][0] * inv0, v1 = o[nt][1] * inv0;
        float v2 = o[nt][2] * inv1, v3 = o[nt][3] * inv1;
        __nv_bfloat16 h0 = __float2bfloat16(v0), h1 = __float2bfloat16(v1);
        __nv_bfloat16 h2 = __float2bfloat16(v2), h3 = __float2bfloat16(v3);
        g_chi[ob0 + c] = h0;     g_chi[ob0 + c + 1] = h1;
        g_chi[ob1 + c] = h2;     g_chi[ob1 + c + 1] = h3;
        g_clo[ob0 + c]     = __float2bfloat16(v0 - __bfloat162float(h0));
        g_clo[ob0 + c + 1] = __float2bfloat16(v1 - __bfloat162float(h1));
        g_clo[ob1 + c]     = __float2bfloat16(v2 - __bfloat162float(h2));
        g_clo[ob1 + c + 1] = __float2bfloat16(v3 - __bfloat162float(h3));
    }
}

// ---------------- log-softmax NLL per row (vectorized) --------------------
__global__ __launch_bounds__(256)
void loss_kernel(const float* __restrict__ logits, const int* __restrict__ target) {
    __shared__ float sm[8];
    int row = blockIdx.x;
    const float4* lr4 = (const float4*)(logits + (size_t)row * VDIM);
    int tid = threadIdx.x, lane = tid & 31, warp = tid >> 5;

    float mx = -1e30f;
#pragma unroll
    for (int it = 0; it < 8; it++) {
        float4 v = lr4[tid + it * 256];
        mx = fmaxf(mx, fmaxf(fmaxf(v.x, v.y), fmaxf(v.z, v.w)));
    }
#pragma unroll
    for (int d = 16; d > 0; d >>= 1) mx = fmaxf(mx, __shfl_xor_sync(0xffffffffu, mx, d));
    if (lane == 0) sm[warp] = mx;
    __syncthreads();
    mx = fmaxf(fmaxf(fmaxf(sm[0], sm[1]), fmaxf(sm[2], sm[3])),
               fmaxf(fmaxf(sm[4], sm[5]), fmaxf(sm[6], sm[7])));
    __syncthreads();

    float se = 0.f;
#pragma unroll
    for (int it = 0; it < 8; it++) {
        float4 v = lr4[tid + it * 256];
        se += __expf(v.x - mx) + __expf(v.y - mx) + __expf(v.z - mx) + __expf(v.w - mx);
    }
#pragma unroll
    for (int d = 16; d > 0; d >>= 1) se += __shfl_xor_sync(0xffffffffu, se, d);
    if (lane == 0) sm[warp] = se;
    __syncthreads();
    if (tid == 0) {
        float tot = sm[0] + sm[1] + sm[2] + sm[3] + sm[4] + sm[5] + sm[6] + sm[7];
        g_nll[row] = logf(tot) + mx - logits[(size_t)row * VDIM + target[row]];
    }
}

__global__ __launch_bounds__(1024)
void reduce_loss_kernel(float* __restrict__ out, long long loss_idx) {
    __shared__ float sm[1024];
    int tid = threadIdx.x;
    float s = 0.f;
    for (int i = tid; i < BT; i += 1024) s += g_nll[i];
    sm[tid] = s; __syncthreads();
    for (int st = 512; st > 0; st >>= 1) {
        if (tid < st) sm[tid] += sm[tid + st];
        __syncthreads();
    }
    if (tid == 0 && loss_idx >= 0)
        out[loss_idx] = sm[0] / (float)BT;
}

// ---------------- launch --------------------------------------------------
extern "C" void kernel_launch(void* const* d_in, const int* in_sizes, int n_in,
                              void* d_out, int out_size) {
    const int*   x      = (const int*)  d_in[0];
    const int*   target = (const int*)  d_in[1];
    const float* embed_w= (const float*)d_in[2];
    const float* pos    = (const float*)d_in[3];
    const float* Wq     = (const float*)d_in[4];
    const float* bq     = (const float*)d_in[5];
    const float* Wk     = (const float*)d_in[6];
    const float* bk     = (const float*)d_in[7];
    const float* Wv     = (const float*)d_in[8];
    const float* bv     = (const float*)d_in[9];
    const float* Wo     = (const float*)d_in[10];
    const float* bo     = (const float*)d_in[11];
    const float* Wu     = (const float*)d_in[12];
    float* out = (float*)d_out;

    float *h, *logits_scratch;
    cudaGetSymbolAddress((void**)&h, g_h);
    cudaGetSymbolAddress((void**)&logits_scratch, g_logits);

    __nv_bfloat16 *ahi, *alo, *qhi, *qlo, *khi, *klo, *vthi, *vtlo, *chi, *clo;
    __nv_bfloat16 *wqhi, *wqlo, *wkhi, *wklo, *wvhi, *wvlo, *wohi, *wolo, *wuhi, *wulo;
    cudaGetSymbolAddress((void**)&ahi,  g_ahi);  cudaGetSymbolAddress((void**)&alo,  g_alo);
    cudaGetSymbolAddress((void**)&qhi,  g_qhi);  cudaGetSymbolAddress((void**)&qlo,  g_qlo);
    cudaGetSymbolAddress((void**)&khi,  g_khi);  cudaGetSymbolAddress((void**)&klo,  g_klo);
    cudaGetSymbolAddress((void**)&vthi, g_vthi); cudaGetSymbolAddress((void**)&vtlo, g_vtlo);
    cudaGetSymbolAddress((void**)&chi,  g_chi);  cudaGetSymbolAddress((void**)&clo,  g_clo);
    cudaGetSymbolAddress((void**)&wqhi, g_wqhi); cudaGetSymbolAddress((void**)&wqlo, g_wqlo);
    cudaGetSymbolAddress((void**)&wkhi, g_wkhi); cudaGetSymbolAddress((void**)&wklo, g_wklo);
    cudaGetSymbolAddress((void**)&wvhi, g_wvhi); cudaGetSymbolAddress((void**)&wvlo, g_wvlo);
    cudaGetSymbolAddress((void**)&wohi, g_wohi); cudaGetSymbolAddress((void**)&wolo, g_wolo);
    cudaGetSymbolAddress((void**)&wuhi, g_wuhi); cudaGetSymbolAddress((void**)&wulo, g_wulo);

    static bool attr_set = false;
    if (!attr_set) {
        cudaFuncSetAttribute(gemm_bf16x3, cudaFuncAttributeMaxDynamicSharedMemorySize, GSMEM);
        cudaFuncSetAttribute(gemm_qkv, cudaFuncAttributeMaxDynamicSharedMemorySize, GSMEM);
        cudaFuncSetAttribute(attn_mma_kernel, cudaFuncAttributeMaxDynamicSharedMemorySize, ASMEM);
        attr_set = true;
    }

    const size_t nlogits = (size_t)BT * VDIM;
    float* logits_dst = ((size_t)out_size >= nlogits) ? out : logits_scratch;
    long long loss_idx;
    if ((size_t)out_size > nlogits)       loss_idx = (long long)nlogits;
    else if ((size_t)out_size < nlogits)  loss_idx = 0;
    else                                  loss_idx = -1;

    // 0) fused weight splits (single launch)
    {
        SplitArgs sa;
        sa.src[0] = Wq; sa.hi[0] = wqhi; sa.lo[0] = wqlo;
        sa.src[1] = Wk; sa.hi[1] = wkhi; sa.lo[1] = wklo;
        sa.src[2] = Wv; sa.hi[2] = wvhi; sa.lo[2] = wvlo;
        sa.src[3] = Wo; sa.hi[3] = wohi; sa.lo[3] = wolo;
        sa.src[4] = Wu; sa.hi[4] = wuhi; sa.lo[4] = wulo;
        split_all_kernel<<<(WTOT + 255) / 256, 256>>>(sa);
    }

    // 1) embedding
    {
        size_t total = (size_t)BT * CDIM;
        embed_kernel<<<(unsigned)((total + 255) / 256), 256>>>(x, embed_w, pos);
    }

    // 2) transformer layers
    dim3 gC(CDIM / 128, BT / 128);       // (8, 32)
    dim3 gQKV(3 * CDIM / 128, BT / 128); // (24, 32)
    for (int l = 0; l < LAYERS; l++) {
        size_t woff = (size_t)l * CDIM * CDIM;
        QKVArgs qa;
        qa.Ahi = ahi; qa.Alo = alo;
        qa.Wh[0] = wqhi + woff; qa.Wl[0] = wqlo + woff;
        qa.Wh[1] = wkhi + woff; qa.Wl[1] = wklo + woff;
        qa.Wh[2] = wvhi + woff; qa.Wl[2] = wvlo + woff;
        qa.bias[0] = bq + l * CDIM; qa.bias[1] = bk + l * CDIM; qa.bias[2] = bv + l * CDIM;
        qa.ohi[0] = qhi;  qa.olo[0] = qlo;
        qa.ohi[1] = khi;  qa.olo[1] = klo;
        qa.ohi[2] = vthi; qa.olo[2] = vtlo;
        gemm_qkv<<<gQKV, GT, GSMEM>>>(qa);

        attn_mma_kernel<<<dim3(NQT, BATCH * NHEAD), 256, ASMEM>>>();

        gemm_bf16x3<<<gC, GT, GSMEM>>>(chi, clo, wohi + woff, wolo + woff,
                                       bo + l * CDIM, h,
                                       h, ahi, alo, BT, CDIM, CDIM);
    }

    // 3) logits = h @ Wu^T
    gemm_bf16x3<<<dim3(VDIM / 128, BT / 128), GT, GSMEM>>>(ahi, alo, wuhi, wulo,
                                                           nullptr, nullptr,
                                                           logits_dst, nullptr, nullptr,
                                                           BT, VDIM, CDIM);

    // 4) loss
    loss_kernel<<<BT, 256>>>(logits_dst, target);
    reduce_loss_kernel<<<1, 1024>>>(out, loss_idx);
}

// round 16
// speedup vs baseline: 1.1142x; 1.1142x over previous
#include <cuda_runtime.h>
#include <cuda_bf16.h>
#include <stdint.h>
#include <math.h>

typedef unsigned int u32;

// ---------------- problem constants (match setup_inputs) ----------------
#define BATCH  2
#define TSEQ   2048
#define CDIM   1024
#define VDIM   8192
#define LAYERS 2
#define NHEAD  16
#define HD     64
#define BT     (BATCH * TSEQ)   // 4096 rows

// ---------------- scratch (device globals: allocation-free) -------------
__device__ float g_h[BT * CDIM];
__device__ float g_logits[(size_t)BT * VDIM];
__device__ float g_nll[BT];

__device__ __nv_bfloat16 g_ahi[BT * CDIM];
__device__ __nv_bfloat16 g_alo[BT * CDIM];
__device__ __nv_bfloat16 g_qhi[BT * CDIM];
__device__ __nv_bfloat16 g_qlo[BT * CDIM];
__device__ __nv_bfloat16 g_khi[BT * CDIM];
__device__ __nv_bfloat16 g_klo[BT * CDIM];
__device__ __nv_bfloat16 g_vthi[BT * CDIM];  // transposed: [(b,c)][token]
__device__ __nv_bfloat16 g_vtlo[BT * CDIM];
__device__ __nv_bfloat16 g_chi[BT * CDIM];
__device__ __nv_bfloat16 g_clo[BT * CDIM];

__device__ __nv_bfloat16 g_wqhi[LAYERS * CDIM * CDIM];
__device__ __nv_bfloat16 g_wqlo[LAYERS * CDIM * CDIM];
__device__ __nv_bfloat16 g_wkhi[LAYERS * CDIM * CDIM];
__device__ __nv_bfloat16 g_wklo[LAYERS * CDIM * CDIM];
__device__ __nv_bfloat16 g_wvhi[LAYERS * CDIM * CDIM];
__device__ __nv_bfloat16 g_wvlo[LAYERS * CDIM * CDIM];
__device__ __nv_bfloat16 g_wohi[LAYERS * CDIM * CDIM];
__device__ __nv_bfloat16 g_wolo[LAYERS * CDIM * CDIM];
__device__ __nv_bfloat16 g_wuhi[(size_t)VDIM * CDIM];
__device__ __nv_bfloat16 g_wulo[(size_t)VDIM * CDIM];

// ---------------- fp32 -> bf16 hi/lo split (weights) ----------------------
__global__ void split_kernel(const float* __restrict__ src,
                             __nv_bfloat16* __restrict__ hi,
                             __nv_bfloat16* __restrict__ lo, size_t n) {
    size_t i = (size_t)blockIdx.x * blockDim.x + threadIdx.x;
    if (i >= n) return;
    float x = src[i];
    __nv_bfloat16 h = __float2bfloat16(x);
    hi[i] = h;
    lo[i] = __float2bfloat16(x - __bfloat162float(h));
}

// ---------------- embedding + positional (+ hi/lo), float4 ----------------
__global__ void embed_kernel(const int* __restrict__ x,
                             const float* __restrict__ embed_w,
                             const float* __restrict__ pos) {
    size_t i4 = ((size_t)blockIdx.x * blockDim.x + threadIdx.x) * 4;
    size_t total = (size_t)BT * CDIM;
    if (i4 >= total) return;
    int c  = (int)(i4 % CDIM);
    size_t bt = i4 / CDIM;
    int t  = (int)(bt % TSEQ);
    int tok = x[bt];
    float4 ew = *(const float4*)&embed_w[(size_t)tok * CDIM + c];
    float4 pw = *(const float4*)&pos[(size_t)t * CDIM + c];
    float v0 = ew.x + pw.x, v1 = ew.y + pw.y, v2 = ew.z + pw.z, v3 = ew.w + pw.w;
    *(float4*)&g_h[i4] = make_float4(v0, v1, v2, v3);
    __nv_bfloat16 h0 = __float2bfloat16(v0), h1 = __float2bfloat16(v1);
    __nv_bfloat16 h2 = __float2bfloat16(v2), h3 = __float2bfloat16(v3);
    __nv_bfloat162 hp0; hp0.x = h0; hp0.y = h1;
    __nv_bfloat162 hp1; hp1.x = h2; hp1.y = h3;
    *(__nv_bfloat162*)&g_ahi[i4]     = hp0;
    *(__nv_bfloat162*)&g_ahi[i4 + 2] = hp1;
    __nv_bfloat162 lp0, lp1;
    lp0.x = __float2bfloat16(v0 - __bfloat162float(h0));
    lp0.y = __float2bfloat16(v1 - __bfloat162float(h1));
    lp1.x = __float2bfloat16(v2 - __bfloat162float(h2));
    lp1.y = __float2bfloat16(v3 - __bfloat162float(h3));
    *(__nv_bfloat162*)&g_alo[i4]     = lp0;
    *(__nv_bfloat162*)&g_alo[i4 + 2] = lp1;
}

// ---------------- shared helpers ------------------------------------------
__device__ __forceinline__ void cp16(u32 s, const void* g) {
    asm volatile("cp.async.cg.shared.global [%0], [%1], 16;\n" :: "r"(s), "l"(g));
}
__device__ __forceinline__ void mma_bf16(float* d, const u32* a, const u32* b) {
    asm volatile(
        "mma.sync.aligned.m16n8k16.row.col.f32.bf16.bf16.f32 "
        "{%0,%1,%2,%3}, {%4,%5,%6,%7}, {%8,%9}, {%0,%1,%2,%3};\n"
        : "+f"(d[0]), "+f"(d[1]), "+f"(d[2]), "+f"(d[3])
        : "r"(a[0]), "r"(a[1]), "r"(a[2]), "r"(a[3]), "r"(b[0]), "r"(b[1]));
}
__device__ __forceinline__ void ldm4(u32* r, u32 a) {
    asm volatile("ldmatrix.sync.aligned.m8n8.x4.shared.b16 {%0,%1,%2,%3}, [%4];"
                 : "=r"(r[0]), "=r"(r[1]), "=r"(r[2]), "=r"(r[3]) : "r"(a));
}
__device__ __forceinline__ u32 pk2(float x, float y) {
    __nv_bfloat162 p = __floats2bfloat162_rn(x, y);
    return *(u32*)&p;
}

// ---------------- GEMM tile config ----------------------------------------
#define GT 256
#define RS      80
#define ARRB    (128 * RS)
#define STAGE   (4 * ARRB)
#define GSMEM   (2 * STAGE)              // 81920

// ---------------- fused QKV GEMM ------------------------------------------
struct QKVArgs {
    const __nv_bfloat16 *Ahi, *Alo;
    const __nv_bfloat16 *Wh[3], *Wl[3];
    const float *bias[3];
    __nv_bfloat16 *ohi[3], *olo[3];
};

__global__ __launch_bounds__(GT)
void gemm_qkv(QKVArgs args) {
    extern __shared__ char smraw[];
    u32 sbase = (u32)__cvta_generic_to_shared(smraw);

    int tid = threadIdx.x;
    int lane = tid & 31, wid = tid >> 5;
    int warp_m = wid & 1, warp_n = wid >> 1;
    int wsel = (int)(blockIdx.x >> 3);          // 0:Q 1:K 2:V
    int m0 = blockIdx.y * 128, n0 = (int)(blockIdx.x & 7) * 128;
    int g = lane >> 2, t2 = (lane & 3) * 2;
    const int N = CDIM, K = CDIM;

    const __nv_bfloat16* Ahi = args.Ahi;
    const __nv_bfloat16* Alo = args.Alo;
    const __nv_bfloat16* Whi = args.Wh[wsel];
    const __nv_bfloat16* Wlo = args.Wl[wsel];

    float acc[4][4][4];
#pragma unroll
    for (int i = 0; i < 4; i++)
#pragma unroll
        for (int j = 0; j < 4; j++)
#pragma unroll
            for (int r = 0; r < 4; r++) acc[i][j][r] = 0.f;

    int NKB = K >> 5;
    auto issue_loads = [&](int kb, int s) {
        int kk = kb << 5;
        u32 st = sbase + s * STAGE;
#pragma unroll
        for (int ii = 0; ii < 8; ii++) {
            int i = tid + ii * GT;
            int arr = i >> 9, rem = i & 511;
            int r = rem >> 2, gg = rem & 3;
            const __nv_bfloat16* src = (arr == 0) ? Ahi : (arr == 1) ? Alo
                                      : (arr == 2) ? Whi : Wlo;
            int row = ((arr < 2) ? m0 : n0) + r;
            u32 dst = st + (u32)arr * ARRB + (u32)(r * RS + gg * 16);
            cp16(dst, src + (size_t)row * K + kk + gg * 8);
        }
    };

    issue_loads(0, 0);
    asm volatile("cp.async.commit_group;\n");
    issue_loads(1, 1);
    asm volatile("cp.async.commit_group;\n");

    for (int kb = 0; kb < NKB; kb++) {
        if (kb + 1 < NKB) asm volatile("cp.async.wait_group 1;\n" ::: "memory");
        else              asm volatile("cp.async.wait_group 0;\n" ::: "memory");
        __syncthreads();
        u32 st = sbase + (kb & 1) * STAGE;

#pragma unroll
        for (int ks = 0; ks < 2; ks++) {
            int kby = ks * 32;
            u32 ah[4][4], al[4][4];
#pragma unroll
            for (int mi = 0; mi < 4; mi++) {
                u32 arow = st + (u32)((warp_m * 64 + mi * 16 + (lane & 15)) * RS
                                      + kby + (lane >> 4) * 16);
                ldm4(ah[mi], arow);
                ldm4(al[mi], arow + ARRB);
            }
            u32 bh[2][4], bl[2][4];
#pragma unroll
            for (int kh = 0; kh < 2; kh++) {
                u32 brow = st + 2 * ARRB + (u32)((warp_n * 32 + lane) * RS
                                                 + kby + kh * 16);
                ldm4(bh[kh], brow);
                ldm4(bl[kh], brow + ARRB);
            }
            u32 bfh[4][2], bfl[4][2];
#pragma unroll
            for (int ni = 0; ni < 4; ni++) {
                bfh[ni][0] = bh[0][ni]; bfh[ni][1] = bh[1][ni];
                bfl[ni][0] = bl[0][ni]; bfl[ni][1] = bl[1][ni];
            }
#pragma unroll
            for (int mi = 0; mi < 4; mi++)
#pragma unroll
                for (int ni = 0; ni < 4; ni++)
                    mma_bf16(acc[mi][ni], ah[mi], bfh[ni]);
#pragma unroll
            for (int mi = 0; mi < 4; mi++)
#pragma unroll
                for (int ni = 0; ni < 4; ni++)
                    mma_bf16(acc[mi][ni], ah[mi], bfl[ni]);
#pragma unroll
            for (int mi = 0; mi < 4; mi++)
#pragma unroll
                for (int ni = 0; ni < 4; ni++)
                    mma_bf16(acc[mi][ni], al[mi], bfh[ni]);
        }
        __syncthreads();
        if (kb + 2 < NKB) {
            issue_loads(kb + 2, kb & 1);
            asm volatile("cp.async.commit_group;\n");
        }
    }

    const float* bias = args.bias[wsel];
    __nv_bfloat16* ohi = args.ohi[wsel];
    __nv_bfloat16* olo = args.olo[wsel];
    int vtrans = (wsel == 2);

    auto emit = [&](int m, int cc, float val) {
        __nv_bfloat16 hb = __float2bfloat16(val);
        __nv_bfloat16 lb = __float2bfloat16(val - __bfloat162float(hb));
        size_t idx = vtrans
            ? ((size_t)((m >> 11) * N + cc)) * TSEQ + (m & 2047)
            : (size_t)m * N + cc;
        ohi[idx] = hb;
        olo[idx] = lb;
    };
#pragma unroll
    for (int mi = 0; mi < 4; mi++) {
        int r0 = m0 + warp_m * 64 + mi * 16 + g;
#pragma unroll
        for (int ni = 0; ni < 4; ni++) {
            int c = n0 + warp_n * 32 + ni * 8 + t2;
            float b0 = bias[c], b1 = bias[c + 1];
            emit(r0, c, acc[mi][ni][0] + b0);
            emit(r0, c + 1, acc[mi][ni][1] + b1);
            emit(r0 + 8, c, acc[mi][ni][2] + b0);
            emit(r0 + 8, c + 1, acc[mi][ni][3] + b1);
        }
    }
}

// ---------------- generic bf16x3 GEMM (Wo, logits) -------------------------
__global__ __launch_bounds__(GT)
void gemm_bf16x3(const __nv_bfloat16* __restrict__ Ahi, const __nv_bfloat16* __restrict__ Alo,
                 const __nv_bfloat16* __restrict__ Whi, const __nv_bfloat16* __restrict__ Wlo,
                 const float* __restrict__ bias, const float* __restrict__ res,
                 float* __restrict__ outf,
                 __nv_bfloat16* __restrict__ ohi, __nv_bfloat16* __restrict__ olo,
                 int M, int N, int K) {
    extern __shared__ char smraw[];
    u32 sbase = (u32)__cvta_generic_to_shared(smraw);

    int tid = threadIdx.x;
    int lane = tid & 31, wid = tid >> 5;
    int warp_m = wid & 1, warp_n = wid >> 1;
    int m0 = blockIdx.y * 128, n0 = blockIdx.x * 128;
    int g = lane >> 2, t2 = (lane & 3) * 2;

    float acc[4][4][4];
#pragma unroll
    for (int i = 0; i < 4; i++)
#pragma unroll
        for (int j = 0; j < 4; j++)
#pragma unroll
            for (int r = 0; r < 4; r++) acc[i][j][r] = 0.f;

    int NKB = K >> 5;
    auto issue_loads = [&](int kb, int s) {
        int kk = kb << 5;
        u32 st = sbase + s * STAGE;
#pragma unroll
        for (int ii = 0; ii < 8; ii++) {
            int i = tid + ii * GT;
            int arr = i >> 9, rem = i & 511;
            int r = rem >> 2, gg = rem & 3;
            const __nv_bfloat16* src = (arr == 0) ? Ahi : (arr == 1) ? Alo
                                      : (arr == 2) ? Whi : Wlo;
            int row = ((arr < 2) ? m0 : n0) + r;
            u32 dst = st + (u32)arr * ARRB + (u32)(r * RS + gg * 16);
            cp16(dst, src + (size_t)row * K + kk + gg * 8);
        }
    };

    issue_loads(0, 0);
    asm volatile("cp.async.commit_group;\n");
    issue_loads(1, 1);
    asm volatile("cp.async.commit_group;\n");

    for (int kb = 0; kb < NKB; kb++) {
        if (kb + 1 < NKB) asm volatile("cp.async.wait_group 1;\n" ::: "memory");
        else              asm volatile("cp.async.wait_group 0;\n" ::: "memory");
        __syncthreads();
        u32 st = sbase + (kb & 1) * STAGE;

#pragma unroll
        for (int ks = 0; ks < 2; ks++) {
            int kby = ks * 32;
            u32 ah[4][4], al[4][4];
#pragma unroll
            for (int mi = 0; mi < 4; mi++) {
                u32 arow = st + (u32)((warp_m * 64 + mi * 16 + (lane & 15)) * RS
                                      + kby + (lane >> 4) * 16);
                ldm4(ah[mi], arow);
                ldm4(al[mi], arow + ARRB);
            }
            u32 bh[2][4], bl[2][4];
#pragma unroll
            for (int kh = 0; kh < 2; kh++) {
                u32 brow = st + 2 * ARRB + (u32)((warp_n * 32 + lane) * RS
                                                 + kby + kh * 16);
                ldm4(bh[kh], brow);
                ldm4(bl[kh], brow + ARRB);
            }
            u32 bfh[4][2], bfl[4][2];
#pragma unroll
            for (int ni = 0; ni < 4; ni++) {
                bfh[ni][0] = bh[0][ni]; bfh[ni][1] = bh[1][ni];
                bfl[ni][0] = bl[0][ni]; bfl[ni][1] = bl[1][ni];
            }
#pragma unroll
            for (int mi = 0; mi < 4; mi++)
#pragma unroll
                for (int ni = 0; ni < 4; ni++)
                    mma_bf16(acc[mi][ni], ah[mi], bfh[ni]);
#pragma unroll
            for (int mi = 0; mi < 4; mi++)
#pragma unroll
                for (int ni = 0; ni < 4; ni++)
                    mma_bf16(acc[mi][ni], ah[mi], bfl[ni]);
#pragma unroll
            for (int mi = 0; mi < 4; mi++)
#pragma unroll
                for (int ni = 0; ni < 4; ni++)
                    mma_bf16(acc[mi][ni], al[mi], bfh[ni]);
        }
        __syncthreads();
        if (kb + 2 < NKB) {
            issue_loads(kb + 2, kb & 1);
            asm volatile("cp.async.commit_group;\n");
        }
    }

    auto emit = [&](int m, int cc, float val) {
        if (outf) outf[(size_t)m * N + cc] = val;
        if (ohi) {
            __nv_bfloat16 hb = __float2bfloat16(val);
            __nv_bfloat16 lb = __float2bfloat16(val - __bfloat162float(hb));
            size_t idx = (size_t)m * N + cc;
            ohi[idx] = hb;
            olo[idx] = lb;
        }
    };
#pragma unroll
    for (int mi = 0; mi < 4; mi++) {
        int r0 = m0 + warp_m * 64 + mi * 16 + g;
#pragma unroll
        for (int ni = 0; ni < 4; ni++) {
            int c = n0 + warp_n * 32 + ni * 8 + t2;
            float v0 = acc[mi][ni][0], v1 = acc[mi][ni][1];
            float v2 = acc[mi][ni][2], v3 = acc[mi][ni][3];
            if (bias) { float b0 = bias[c], b1 = bias[c + 1]; v0 += b0; v1 += b1; v2 += b0; v3 += b1; }
            if (res) {
                v0 += res[(size_t)r0 * N + c];       v1 += res[(size_t)r0 * N + c + 1];
                v2 += res[(size_t)(r0 + 8) * N + c]; v3 += res[(size_t)(r0 + 8) * N + c + 1];
            }
            emit(r0, c, v0);     emit(r0, c + 1, v1);
            emit(r0 + 8, c, v2); emit(r0 + 8, c + 1, v3);
        }
    }
}

// ---------------- MMA flash attention (R13 config: 512 CTAs, 1/SM) ---------
#define APAD 72
#define QSZB (128 * APAD * 2)
#define KSZB (64 * APAD * 2)
#define STGB (4 * KSZB)
#define ASMEM (2 * QSZB + 2 * STGB)  // 110592
#define NQT  (TSEQ / 128)            // 16

__global__ __launch_bounds__(256)
void attn_mma_kernel() {
    extern __shared__ char araw[];
    u32 sb = (u32)__cvta_generic_to_shared(araw);
    __nv_bfloat16* Qh = (__nv_bfloat16*)araw;
    __nv_bfloat16* Ql = Qh + 128 * APAD;

    int tid = threadIdx.x, lane = tid & 31, wq = tid >> 5;
    int g = lane >> 2, t = lane & 3;
    int b = blockIdx.y >> 4, hh = blockIdx.y & 15;
    int qt = (int)(gridDim.x - 1 - blockIdx.x);   // longest CTAs first
    int nkv = 2 * qt + 2;

    {
        size_t qb = ((size_t)(b * TSEQ + qt * 128)) * CDIM + hh * HD;
#pragma unroll
        for (int ii = 0; ii < 8; ii++) {
            int i = tid + ii * 256;
            int arr = i >> 10, rem = i & 1023;
            int r = rem >> 3, gg = rem & 7;
            const __nv_bfloat16* src = (arr ? g_qlo : g_qhi) + qb + (size_t)r * CDIM + gg * 8;
            cp16(sb + (u32)arr * QSZB + (u32)(r * (APAD * 2) + gg * 16), src);
        }
    }
    auto load_kv = [&](int kt, int st) {
        u32 base = sb + 2 * QSZB + (u32)st * STGB;
        size_t kb = ((size_t)(b * TSEQ + kt * 64)) * CDIM + hh * HD;
        size_t vb = ((size_t)(b * CDIM + hh * HD)) * TSEQ + kt * 64;
#pragma unroll
        for (int ii = 0; ii < 8; ii++) {
            int i = tid + ii * 256;
            int arr = i >> 9, rem = i & 511;
            int r = rem >> 3, gg = rem & 7;
            const __nv_bfloat16* src;
            if (arr == 0)      src = g_khi  + kb + (size_t)r * CDIM + gg * 8;
            else if (arr == 1) src = g_klo  + kb + (size_t)r * CDIM + gg * 8;
            else if (arr == 2) src = g_vthi + vb + (size_t)r * TSEQ + gg * 8;
            else               src = g_vtlo + vb + (size_t)r * TSEQ + gg * 8;
            cp16(base + (u32)arr * KSZB + (u32)(r * (APAD * 2) + gg * 16), src);
        }
    };
    load_kv(0, 0);
    asm volatile("cp.async.commit_group;\n");   // group: Q + KV0
    load_kv(1, 1);
    asm volatile("cp.async.commit_group;\n");   // group: KV1

    u32 qah[4][4], qal[4][4];
    float m0r = -1e30f, m1r = -1e30f, l0 = 0.f, l1 = 0.f;
    float o[8][4];
#pragma unroll
    for (int nt = 0; nt < 8; nt++)
#pragma unroll
        for (int i = 0; i < 4; i++) o[nt][i] = 0.f;

    for (int kt = 0; kt < nkv; kt++) {
        if (kt + 1 < nkv) asm volatile("cp.async.wait_group 1;\n" ::: "memory");
        else              asm volatile("cp.async.wait_group 0;\n" ::: "memory");
        __syncthreads();

        if (kt == 0) {
#pragma unroll
            for (int kb2 = 0; kb2 < 4; kb2++) {
                int r = wq * 16 + g, kk = kb2 * 16 + t * 2;
                qah[kb2][0] = *(const u32*)&Qh[r * APAD + kk];
                qah[kb2][1] = *(const u32*)&Qh[(r + 8) * APAD + kk];
                qah[kb2][2] = *(const u32*)&Qh[r * APAD + kk + 8];
                qah[kb2][3] = *(const u32*)&Qh[(r + 8) * APAD + kk + 8];
                qal[kb2][0] = *(const u32*)&Ql[r * APAD + kk];
                qal[kb2][1] = *(const u32*)&Ql[(r + 8) * APAD + kk];
                qal[kb2][2] = *(const u32*)&Ql[r * APAD + kk + 8];
                qal[kb2][3] = *(const u32*)&Ql[(r + 8) * APAD + kk + 8];
            }
        }

        __nv_bfloat16* Kh = (__nv_bfloat16*)(araw + 2 * QSZB + (kt & 1) * STGB);
        __nv_bfloat16* Kl = Kh + 64 * APAD;
        __nv_bfloat16* Vh = Kl + 64 * APAD;
        __nv_bfloat16* Vl = Vh + 64 * APAD;

        float s[8][4];
#pragma unroll
        for (int nt = 0; nt < 8; nt++)
#pragma unroll
            for (int i = 0; i < 4; i++) s[nt][i] = 0.f;

#pragma unroll
        for (int kb2 = 0; kb2 < 4; kb2++) {
            u32 kh2[8][2], kl2[8][2];
#pragma unroll
            for (int nt = 0; nt < 8; nt++) {
                int off = (nt * 8 + g) * APAD + kb2 * 16 + t * 2;
                kh2[nt][0] = *(const u32*)&Kh[off];
                kh2[nt][1] = *(const u32*)&Kh[off + 8];
                kl2[nt][0] = *(const u32*)&Kl[off];
                kl2[nt][1] = *(const u32*)&Kl[off + 8];
            }
#pragma unroll
            for (int nt = 0; nt < 8; nt++) mma_bf16(s[nt], qah[kb2], kh2[nt]);
#pragma unroll
            for (int nt = 0; nt < 8; nt++) mma_bf16(s[nt], qah[kb2], kl2[nt]);
#pragma unroll
            for (int nt = 0; nt < 8; nt++) mma_bf16(s[nt], qal[kb2], kh2[nt]);
        }

#pragma unroll
        for (int nt = 0; nt < 8; nt++) {
            s[nt][0] *= 0.125f; s[nt][1] *= 0.125f;
            s[nt][2] *= 0.125f; s[nt][3] *= 0.125f;
        }
        if (kt >= 2 * qt) {
            int rg0 = qt * 128 + wq * 16 + g, rg1 = rg0 + 8;
#pragma unroll
            for (int nt = 0; nt < 8; nt++) {
                int cg = kt * 64 + nt * 8 + t * 2;
                if (cg > rg0)     s[nt][0] = -1e30f;
                if (cg + 1 > rg0) s[nt][1] = -1e30f;
                if (cg > rg1)     s[nt][2] = -1e30f;
                if (cg + 1 > rg1) s[nt][3] = -1e30f;
            }
        }

        float tm0 = -1e30f, tm1 = -1e30f;
#pragma unroll
        for (int nt = 0; nt < 8; nt++) {
            tm0 = fmaxf(tm0, fmaxf(s[nt][0], s[nt][1]));
            tm1 = fmaxf(tm1, fmaxf(s[nt][2], s[nt][3]));
        }
        tm0 = fmaxf(tm0, __shfl_xor_sync(0xffffffffu, tm0, 1));
        tm0 = fmaxf(tm0, __shfl_xor_sync(0xffffffffu, tm0, 2));
        tm1 = fmaxf(tm1, __shfl_xor_sync(0xffffffffu, tm1, 1));
        tm1 = fmaxf(tm1, __shfl_xor_sync(0xffffffffu, tm1, 2));

        float mn0 = fmaxf(m0r, tm0), mn1 = fmaxf(m1r, tm1);
        float cf0 = __expf(m0r - mn0), cf1 = __expf(m1r - mn1);
        l0 *= cf0; l1 *= cf1;
#pragma unroll
        for (int nt = 0; nt < 8; nt++) {
            o[nt][0] *= cf0; o[nt][1] *= cf0;
            o[nt][2] *= cf1; o[nt][3] *= cf1;
        }
        m0r = mn0; m1r = mn1;

        float rs0 = 0.f, rs1 = 0.f;
#pragma unroll
        for (int nt = 0; nt < 8; nt++) {
            s[nt][0] = __expf(s[nt][0] - mn0);
            s[nt][1] = __expf(s[nt][1] - mn0);
            s[nt][2] = __expf(s[nt][2] - mn1);
            s[nt][3] = __expf(s[nt][3] - mn1);
            rs0 += s[nt][0] + s[nt][1];
            rs1 += s[nt][2] + s[nt][3];
        }
        rs0 += __shfl_xor_sync(0xffffffffu, rs0, 1);
        rs0 += __shfl_xor_sync(0xffffffffu, rs0, 2);
        rs1 += __shfl_xor_sync(0xffffffffu, rs1, 1);
        rs1 += __shfl_xor_sync(0xffffffffu, rs1, 2);
        l0 += rs0; l1 += rs1;

        u32 pah[4][4];
#pragma unroll
        for (int kb2 = 0; kb2 < 4; kb2++) {
            float* sa = s[2 * kb2];
            float* sb2 = s[2 * kb2 + 1];
            pah[kb2][0] = pk2(sa[0], sa[1]);
            pah[kb2][1] = pk2(sa[2], sa[3]);
            pah[kb2][2] = pk2(sb2[0], sb2[1]);
            pah[kb2][3] = pk2(sb2[2], sb2[3]);
        }

#pragma unroll
        for (int kb2 = 0; kb2 < 4; kb2++) {
            u32 vh2[8][2], vl2[8][2];
#pragma unroll
            for (int nt = 0; nt < 8; nt++) {
                int off = (nt * 8 + g) * APAD + kb2 * 16 + t * 2;
                vh2[nt][0] = *(const u32*)&Vh[off];
                vh2[nt][1] = *(const u32*)&Vh[off + 8];
                vl2[nt][0] = *(const u32*)&Vl[off];
                vl2[nt][1] = *(const u32*)&Vl[off + 8];
            }
#pragma unroll
            for (int nt = 0; nt < 8; nt++) mma_bf16(o[nt], pah[kb2], vh2[nt]);
#pragma unroll
            for (int nt = 0; nt < 8; nt++) mma_bf16(o[nt], pah[kb2], vl2[nt]);
        }

        __syncthreads();
        if (kt + 2 < nkv) {
            load_kv(kt + 2, kt & 1);
            asm volatile("cp.async.commit_group;\n");
        }
    }

    float inv0 = 1.0f / l0, inv1 = 1.0f / l1;
    int r0 = qt * 128 + wq * 16 + g;
    size_t ob0 = ((size_t)(b * TSEQ + r0)) * CDIM + hh * HD;
    size_t ob1 = ((size_t)(b * TSEQ + r0 + 8)) * CDIM + hh * HD;
#pragma unroll
    for (int nt = 0; nt < 8; nt++) {
        int c = nt * 8 + t * 2;
        float v0 = o[nt][0] * inv0, v1 = o[nt][1] * inv0;
        float v2 = o[nt][2] * inv1, v3 = o[nt][3] * inv1;
        __nv_bfloat16 h0 = __float2bfloat16(v0), h1 = __float2bfloat16(v1);
        __nv_bfloat16 h2 = __float2bfloat16(v2), h3 = __float2bfloat16(v3);
        g_chi[ob0 + c] = h0;     g_chi[ob0 + c + 1] = h1;
        g_chi[ob1 + c] = h2;     g_chi[ob1 + c + 1] = h3;
        g_clo[ob0 + c]     = __float2bfloat16(v0 - __bfloat162float(h0));
        g_clo[ob0 + c + 1] = __float2bfloat16(v1 - __bfloat162float(h1));
        g_clo[ob1 + c]     = __float2bfloat16(v2 - __bfloat162float(h2));
        g_clo[ob1 + c + 1] = __float2bfloat16(v3 - __bfloat162float(h3));
    }
}

// ---------------- log-softmax NLL per row (vectorized) --------------------
__global__ __launch_bounds__(256)
void loss_kernel(const float* __restrict__ logits, const int* __restrict__ target) {
    __shared__ float sm[8];
    int row = blockIdx.x;
    const float4* lr4 = (const float4*)(logits + (size_t)row * VDIM);
    int tid = threadIdx.x, lane = tid & 31, warp = tid >> 5;

    float mx = -1e30f;
#pragma unroll
    for (int it = 0; it < 8; it++) {
        float4 v = lr4[tid + it * 256];
        mx = fmaxf(mx, fmaxf(fmaxf(v.x, v.y), fmaxf(v.z, v.w)));
    }
#pragma unroll
    for (int d = 16; d > 0; d >>= 1) mx = fmaxf(mx, __shfl_xor_sync(0xffffffffu, mx, d));
    if (lane == 0) sm[warp] = mx;
    __syncthreads();
    mx = fmaxf(fmaxf(fmaxf(sm[0], sm[1]), fmaxf(sm[2], sm[3])),
               fmaxf(fmaxf(sm[4], sm[5]), fmaxf(sm[6], sm[7])));
    __syncthreads();

    float se = 0.f;
#pragma unroll
    for (int it = 0; it < 8; it++) {
        float4 v = lr4[tid + it * 256];
        se += __expf(v.x - mx) + __expf(v.y - mx) + __expf(v.z - mx) + __expf(v.w - mx);
    }
#pragma unroll
    for (int d = 16; d > 0; d >>= 1) se += __shfl_xor_sync(0xffffffffu, se, d);
    if (lane == 0) sm[warp] = se;
    __syncthreads();
    if (tid == 0) {
        float tot = sm[0] + sm[1] + sm[2] + sm[3] + sm[4] + sm[5] + sm[6] + sm[7];
        g_nll[row] = logf(tot) + mx - logits[(size_t)row * VDIM + target[row]];
    }
}

__global__ __launch_bounds__(1024)
void reduce_loss_kernel(float* __restrict__ out, long long loss_idx) {
    __shared__ float sm[1024];
    int tid = threadIdx.x;
    float s = 0.f;
    for (int i = tid; i < BT; i += 1024) s += g_nll[i];
    sm[tid] = s; __syncthreads();
    for (int st = 512; st > 0; st >>= 1) {
        if (tid < st) sm[tid] += sm[tid + st];
        __syncthreads();
    }
    if (tid == 0 && loss_idx >= 0)
        out[loss_idx] = sm[0] / (float)BT;
}

// ---------------- launch --------------------------------------------------
extern "C" void kernel_launch(void* const* d_in, const int* in_sizes, int n_in,
                              void* d_out, int out_size) {
    const int*   x      = (const int*)  d_in[0];
    const int*   target = (const int*)  d_in[1];
    const float* embed_w= (const float*)d_in[2];
    const float* pos    = (const float*)d_in[3];
    const float* Wq     = (const float*)d_in[4];
    const float* bq     = (const float*)d_in[5];
    const float* Wk     = (const float*)d_in[6];
    const float* bk     = (const float*)d_in[7];
    const float* Wv     = (const float*)d_in[8];
    const float* bv     = (const float*)d_in[9];
    const float* Wo     = (const float*)d_in[10];
    const float* bo     = (const float*)d_in[11];
    const float* Wu     = (const float*)d_in[12];
    float* out = (float*)d_out;

    float *h, *logits_scratch;
    cudaGetSymbolAddress((void**)&h, g_h);
    cudaGetSymbolAddress((void**)&logits_scratch, g_logits);

    __nv_bfloat16 *ahi, *alo, *qhi, *qlo, *khi, *klo, *vthi, *vtlo, *chi, *clo;
    __nv_bfloat16 *wqhi, *wqlo, *wkhi, *wklo, *wvhi, *wvlo, *wohi, *wolo, *wuhi, *wulo;
    cudaGetSymbolAddress((void**)&ahi,  g_ahi);  cudaGetSymbolAddress((void**)&alo,  g_alo);
    cudaGetSymbolAddress((void**)&qhi,  g_qhi);  cudaGetSymbolAddress((void**)&qlo,  g_qlo);
    cudaGetSymbolAddress((void**)&khi,  g_khi);  cudaGetSymbolAddress((void**)&klo,  g_klo);
    cudaGetSymbolAddress((void**)&vthi, g_vthi); cudaGetSymbolAddress((void**)&vtlo, g_vtlo);
    cudaGetSymbolAddress((void**)&chi,  g_chi);  cudaGetSymbolAddress((void**)&clo,  g_clo);
    cudaGetSymbolAddress((void**)&wqhi, g_wqhi); cudaGetSymbolAddress((void**)&wqlo, g_wqlo);
    cudaGetSymbolAddress((void**)&wkhi, g_wkhi); cudaGetSymbolAddress((void**)&wklo, g_wklo);
    cudaGetSymbolAddress((void**)&wvhi, g_wvhi); cudaGetSymbolAddress((void**)&wvlo, g_wvlo);
    cudaGetSymbolAddress((void**)&wohi, g_wohi); cudaGetSymbolAddress((void**)&wolo, g_wolo);
    cudaGetSymbolAddress((void**)&wuhi, g_wuhi); cudaGetSymbolAddress((void**)&wulo, g_wulo);

    static bool attr_set = false;
    if (!attr_set) {
        cudaFuncSetAttribute(gemm_bf16x3, cudaFuncAttributeMaxDynamicSharedMemorySize, GSMEM);
        cudaFuncSetAttribute(gemm_qkv, cudaFuncAttributeMaxDynamicSharedMemorySize, GSMEM);
        cudaFuncSetAttribute(attn_mma_kernel, cudaFuncAttributeMaxDynamicSharedMemorySize, ASMEM);
        attr_set = true;
    }

    const size_t nlogits = (size_t)BT * VDIM;
    float* logits_dst = ((size_t)out_size >= nlogits) ? out : logits_scratch;
    long long loss_idx;
    if ((size_t)out_size > nlogits)       loss_idx = (long long)nlogits;
    else if ((size_t)out_size < nlogits)  loss_idx = 0;
    else                                  loss_idx = -1;

    // 0) weight splits (separate launches — R13 configuration)
    {
        size_t nw = (size_t)LAYERS * CDIM * CDIM;
        unsigned gb = (unsigned)((nw + 255) / 256);
        split_kernel<<<gb, 256>>>(Wq, wqhi, wqlo, nw);
        split_kernel<<<gb, 256>>>(Wk, wkhi, wklo, nw);
        split_kernel<<<gb, 256>>>(Wv, wvhi, wvlo, nw);
        split_kernel<<<gb, 256>>>(Wo, wohi, wolo, nw);
        size_t nu = (size_t)VDIM * CDIM;
        split_kernel<<<(unsigned)((nu + 255) / 256), 256>>>(Wu, wuhi, wulo, nu);
    }

    // 1) embedding (float4 vectorized)
    {
        size_t total = (size_t)BT * CDIM / 4;
        embed_kernel<<<(unsigned)((total + 255) / 256), 256>>>(x, embed_w, pos);
    }

    // 2) transformer layers
    dim3 gC(CDIM / 128, BT / 128);       // (8, 32)
    dim3 gQKV(3 * CDIM / 128, BT / 128); // (24, 32)
    for (int l = 0; l < LAYERS; l++) {
        size_t woff = (size_t)l * CDIM * CDIM;
        QKVArgs qa;
        qa.Ahi = ahi; qa.Alo = alo;
        qa.Wh[0] = wqhi + woff; qa.Wl[0] = wqlo + woff;
        qa.Wh[1] = wkhi + woff; qa.Wl[1] = wklo + woff;
        qa.Wh[2] = wvhi + woff; qa.Wl[2] = wvlo + woff;
        qa.bias[0] = bq + l * CDIM; qa.bias[1] = bk + l * CDIM; qa.bias[2] = bv + l * CDIM;
        qa.ohi[0] = qhi;  qa.olo[0] = qlo;
        qa.ohi[1] = khi;  qa.olo[1] = klo;
        qa.ohi[2] = vthi; qa.olo[2] = vtlo;
        gemm_qkv<<<gQKV, GT, GSMEM>>>(qa);

        attn_mma_kernel<<<dim3(NQT, BATCH * NHEAD), 256, ASMEM>>>();

        gemm_bf16x3<<<gC, GT, GSMEM>>>(chi, clo, wohi + woff, wolo + woff,
                                       bo + l * CDIM, h,
                                       h, ahi, alo, BT, CDIM, CDIM);
    }

    // 3) logits = h @ Wu^T
    gemm_bf16x3<<<dim3(VDIM / 128, BT / 128), GT, GSMEM>>>(ahi, alo, wuhi, wulo,
                                                           nullptr, nullptr,
                                                           logits_dst, nullptr, nullptr,
                                                           BT, VDIM, CDIM);

    // 4) loss
    loss_kernel<<<BT, 256>>>(logits_dst, target);
    reduce_loss_kernel<<<1, 1024>>>(out, loss_idx);
}